// round 2
// baseline (speedup 1.0000x reference)
#include <cuda_runtime.h>
#include <cuda_bf16.h>

// SymmetryAwareLossLoop: mean over B of min over (C,S) geodesic angle between
// R_pred[b,c] and R_s @ R_gt[b], for the 12 proper rotations of P622.
//
// tr(R_pred (R_s R_gt)^T) = <R_s, P> with P = R_pred R_gt^T.
// P622 traces reduce to closed form with cos/sin of k*pi/3, and the 12 values
// come in +/- pairs, so max over s is 6 fabs + maxes. acos is monotone
// decreasing -> min theta = acos(clip(max tr ...)), one acosf per warp.
//
// Single fused kernel: fence+counter "last block" pattern replaces the second
// launch (which profiled at 4.26us of pure overhead). The counter is reset to
// 0 by the last block so every graph replay starts clean; the final sum is a
// fixed-order tree, so the output is bitwise deterministic.

#define B_TOTAL   16384
#define C_CAND    32
#define WARPS_PB  8
#define THREADS   (WARPS_PB * 32)
#define NBLOCKS   (B_TOTAL / WARPS_PB)   // 2048

__device__ float        g_partials[NBLOCKS];
__device__ unsigned int g_count = 0;

__global__ __launch_bounds__(THREADS)
void sym_loss_fused(const float* __restrict__ pred,   // (B, C, 3, 3)
                    const float* __restrict__ gt,     // (B, 3, 3)
                    float* __restrict__ out)
{
    __shared__ float sp[WARPS_PB * C_CAND * 9];   // 2304 floats
    __shared__ float sg[WARPS_PB * 9];            // 72 floats
    __shared__ float swarp[WARPS_PB];
    __shared__ bool  sIsLast;

    const int tid   = threadIdx.x;
    const int bBase = blockIdx.x * WARPS_PB;

    // Coalesced float4 staging of this block's R_pred slab (576 f4)
    {
        const float4* src = reinterpret_cast<const float4*>(pred + (size_t)bBase * C_CAND * 9);
        float4* dst = reinterpret_cast<float4*>(sp);
        #pragma unroll
        for (int i = tid; i < (WARPS_PB * C_CAND * 9) / 4; i += THREADS)
            dst[i] = src[i];
    }
    // R_gt slab: 72 floats = 18 f4
    {
        const float4* src = reinterpret_cast<const float4*>(gt + (size_t)bBase * 9);
        float4* dst = reinterpret_cast<float4*>(sg);
        if (tid < (WARPS_PB * 9) / 4) dst[tid] = src[tid];
    }
    __syncthreads();

    const int w = tid >> 5;        // warp = local batch index
    const int c = tid & 31;        // lane = candidate

    const float* pr = sp + (w * C_CAND + c) * 9;  // stride-9 LDS: conflict-free
    const float* g  = sg + w * 9;                 // warp-uniform: broadcast

    const float g0 = g[0], g1 = g[1], g2 = g[2];
    const float g3 = g[3], g4 = g[4], g5 = g[5];
    const float g6 = g[6], g7 = g[7], g8 = g[8];

    const float p0 = pr[0], p1 = pr[1], p2 = pr[2];
    const float p3 = pr[3], p4 = pr[4], p5 = pr[5];
    const float p6 = pr[6], p7 = pr[7], p8 = pr[8];

    // Needed entries of P = R_pred * R_gt^T
    const float P00 = fmaf(p0, g0, fmaf(p1, g1, p2 * g2));
    const float P01 = fmaf(p0, g3, fmaf(p1, g4, p2 * g5));
    const float P10 = fmaf(p3, g0, fmaf(p4, g1, p5 * g2));
    const float P11 = fmaf(p3, g3, fmaf(p4, g4, p5 * g5));
    const float P22 = fmaf(p6, g6, fmaf(p7, g7, p8 * g8));

    const float h  = 0.8660254037844386f;   // sin(pi/3)
    const float A  = P00 + P11;
    const float Bv = P10 - P01;
    const float D  = P00 - P11;
    const float E  = P01 + P10;

    // max trace over the 6 z-rotations (+/- pairs)
    const float mz = fmaxf(fabsf(A),
                     fmaxf(fabsf(fmaf(h, Bv,  0.5f * A)),
                           fabsf(fmaf(h, Bv, -0.5f * A))));
    // max trace over the 6 two-fold axes
    const float m2 = fmaxf(fabsf(D),
                     fmaxf(fabsf(fmaf(h, E,  0.5f * D)),
                           fabsf(fmaf(h, E, -0.5f * D))));

    float maxtr = fmaxf(mz + P22, m2 - P22);   // max over all 12 symmetries

    #pragma unroll
    for (int off = 16; off > 0; off >>= 1)
        maxtr = fmaxf(maxtr, __shfl_xor_sync(0xFFFFFFFFu, maxtr, off));

    if (c == 0) {
        float cosv = (maxtr - 1.0f) * 0.5f;
        cosv = fminf(fmaxf(cosv, -1.0f + 1e-7f), 1.0f - 1e-7f);
        swarp[w] = acosf(cosv);                 // min theta for this batch element
    }
    __syncthreads();

    if (tid == 0) {
        float s = 0.0f;
        #pragma unroll
        for (int i = 0; i < WARPS_PB; ++i) s += swarp[i];
        g_partials[blockIdx.x] = s;
        __threadfence();
        unsigned int old = atomicAdd(&g_count, 1u);
        sIsLast = (old == (unsigned int)(NBLOCKS - 1));
    }
    __syncthreads();

    if (sIsLast) {
        __threadfence();   // acquire: see all blocks' partials
        float s = 0.0f;
        #pragma unroll
        for (int i = tid; i < NBLOCKS; i += THREADS)
            s += g_partials[i];                 // fixed order per thread
        #pragma unroll
        for (int off = 16; off > 0; off >>= 1)
            s += __shfl_xor_sync(0xFFFFFFFFu, s, off);
        if ((tid & 31) == 0) swarp[tid >> 5] = s;   // reuse smem (8 warps)
        __syncthreads();
        if (tid == 0) {
            float t = 0.0f;
            #pragma unroll
            for (int i = 0; i < WARPS_PB; ++i) t += swarp[i];
            out[0] = t / (float)B_TOTAL;
            g_count = 0;                        // reset for next graph replay
        }
    }
}

extern "C" void kernel_launch(void* const* d_in, const int* in_sizes, int n_in,
                              void* d_out, int out_size)
{
    const float* pred = (const float*)d_in[0];   // (B, C, 3, 3)
    const float* gt   = (const float*)d_in[1];   // (B, 3, 3)
    // d_in[2] = rot_mats: P622 rotations, folded into closed-form constants.
    float* out = (float*)d_out;

    sym_loss_fused<<<NBLOCKS, THREADS>>>(pred, gt, out);
}

// round 4
// speedup vs baseline: 1.0239x; 1.0239x over previous
#include <cuda_runtime.h>
#include <cuda_bf16.h>

// SymmetryAwareLossLoop: mean over B of min over (C,S) geodesic angle between
// R_pred[b,c] and R_s @ R_gt[b], for the 12 proper rotations of P622.
//
// tr(R_pred (R_s R_gt)^T) = <R_s, P> with P = R_pred R_gt^T; the 12 P622
// traces collapse to closed form (+/- pairs), acos is monotone decreasing ->
// one acosf per warp.
//
// R3: no smem staging. Thread=(b,c), 9 direct LDGs per thread (MLP=9, every
// 32B sector fully consumed across the warp), no load->compute barrier.
// Single fused kernel with fence+counter last-block final reduction
// (deterministic fixed-order sums; counter reset for graph replay).

#define B_TOTAL   16384
#define C_CAND    32
#define WARPS_PB  8
#define THREADS   (WARPS_PB * 32)
#define NBLOCKS   (B_TOTAL / WARPS_PB)   // 2048

__device__ float        g_partials[NBLOCKS];
__device__ unsigned int g_count = 0;

__global__ __launch_bounds__(THREADS)
void sym_loss_fused(const float* __restrict__ pred,   // (B, C, 3, 3)
                    const float* __restrict__ gt,     // (B, 3, 3)
                    float* __restrict__ out)
{
    __shared__ float swarp[WARPS_PB];
    __shared__ bool  sIsLast;

    const int tid = threadIdx.x;
    const int w   = tid >> 5;                       // warp = local batch
    const int c   = tid & 31;                       // lane = candidate
    const int b   = blockIdx.x * WARPS_PB + w;      // global batch

    const float* __restrict__ pr = pred + ((size_t)b * C_CAND + c) * 9;
    const float* __restrict__ g  = gt   + (size_t)b * 9;

    // 9 independent LDGs per thread: warp covers a contiguous 9216B slab,
    // every fetched sector fully used. ptxas front-batches these (MLP~9).
    const float p0 = __ldg(pr + 0), p1 = __ldg(pr + 1), p2 = __ldg(pr + 2);
    const float p3 = __ldg(pr + 3), p4 = __ldg(pr + 4), p5 = __ldg(pr + 5);
    const float p6 = __ldg(pr + 6), p7 = __ldg(pr + 7), p8 = __ldg(pr + 8);

    // warp-uniform gt loads (broadcast; gt is only 0.6 MB total)
    const float g0 = __ldg(g + 0), g1 = __ldg(g + 1), g2 = __ldg(g + 2);
    const float g3 = __ldg(g + 3), g4 = __ldg(g + 4), g5 = __ldg(g + 5);
    const float g6 = __ldg(g + 6), g7 = __ldg(g + 7), g8 = __ldg(g + 8);

    // Needed entries of P = R_pred * R_gt^T
    const float P00 = fmaf(p0, g0, fmaf(p1, g1, p2 * g2));
    const float P01 = fmaf(p0, g3, fmaf(p1, g4, p2 * g5));
    const float P10 = fmaf(p3, g0, fmaf(p4, g1, p5 * g2));
    const float P11 = fmaf(p3, g3, fmaf(p4, g4, p5 * g5));
    const float P22 = fmaf(p6, g6, fmaf(p7, g7, p8 * g8));

    const float h  = 0.8660254037844386f;   // sin(pi/3)
    const float A  = P00 + P11;
    const float Bv = P10 - P01;
    const float D  = P00 - P11;
    const float E  = P01 + P10;

    // max trace over the 6 z-rotations (+/- pairs)
    const float mz = fmaxf(fabsf(A),
                     fmaxf(fabsf(fmaf(h, Bv,  0.5f * A)),
                           fabsf(fmaf(h, Bv, -0.5f * A))));
    // max trace over the 6 two-fold axes
    const float m2 = fmaxf(fabsf(D),
                     fmaxf(fabsf(fmaf(h, E,  0.5f * D)),
                           fabsf(fmaf(h, E, -0.5f * D))));

    float maxtr = fmaxf(mz + P22, m2 - P22);   // max over all 12 symmetries

    #pragma unroll
    for (int off = 16; off > 0; off >>= 1)
        maxtr = fmaxf(maxtr, __shfl_xor_sync(0xFFFFFFFFu, maxtr, off));

    if (c == 0) {
        float cosv = (maxtr - 1.0f) * 0.5f;
        cosv = fminf(fmaxf(cosv, -1.0f + 1e-7f), 1.0f - 1e-7f);
        swarp[w] = acosf(cosv);                 // min theta for this batch element
    }
    __syncthreads();

    if (tid == 0) {
        float s = 0.0f;
        #pragma unroll
        for (int i = 0; i < WARPS_PB; ++i) s += swarp[i];
        g_partials[blockIdx.x] = s;
        __threadfence();
        unsigned int old = atomicAdd(&g_count, 1u);
        sIsLast = (old == (unsigned int)(NBLOCKS - 1));
    }
    __syncthreads();

    if (sIsLast) {
        __threadfence();   // acquire: see all blocks' partials
        float s = 0.0f;
        #pragma unroll
        for (int i = tid; i < NBLOCKS; i += THREADS)
            s += g_partials[i];                 // fixed order per thread
        #pragma unroll
        for (int off = 16; off > 0; off >>= 1)
            s += __shfl_xor_sync(0xFFFFFFFFu, s, off);
        if ((tid & 31) == 0) swarp[tid >> 5] = s;
        __syncthreads();
        if (tid == 0) {
            float t = 0.0f;
            #pragma unroll
            for (int i = 0; i < WARPS_PB; ++i) t += swarp[i];
            out[0] = t / (float)B_TOTAL;
            g_count = 0;                        // reset for next graph replay
        }
    }
}

extern "C" void kernel_launch(void* const* d_in, const int* in_sizes, int n_in,
                              void* d_out, int out_size)
{
    const float* pred = (const float*)d_in[0];   // (B, C, 3, 3)
    const float* gt   = (const float*)d_in[1];   // (B, 3, 3)
    // d_in[2] = rot_mats: P622 rotations, folded into closed-form constants.
    float* out = (float*)d_out;

    sym_loss_fused<<<NBLOCKS, THREADS>>>(pred, gt, out);
}